// round 2
// baseline (speedup 1.0000x reference)
#include <cuda_runtime.h>

#define B 8
#define L 512
#define HID 768
#define NH 12
#define D 64
#define TH 32
#define TE 64
#define TT 96          // TH + TE
#define BH (B*NH)      // 96
#define ROWS (B*L)     // 4096

// ---------------- scratch (__device__ globals; no allocs allowed) ----------
__device__ float g_Q[BH*L*D];     // [bh][l][d]
__device__ float g_K[BH*L*D];
__device__ float g_V[BH*L*D];
__device__ float g_P[BH*L*TT];    // per-row bias table
__device__ float g_AO[ROWS*HID];  // attention output pre-Wo, [b*l][h*64+d]

// ---------------- GEMM: C = A[4096,768] @ W[768,768] + bias ----------------
#define GTM 128
#define GTN 64
#define GTK 16

__global__ __launch_bounds__(256) void gemm_kernel(
    const float* __restrict__ A, const float* __restrict__ W,
    const float* __restrict__ bias, float* __restrict__ Cout, int headLayout)
{
    __shared__ float As[GTK][GTM + 4];   // A tile transposed: As[k][row]
    __shared__ float Bs[GTK][GTN];       // Bs[k][col]
    const int tid = threadIdx.x;
    const int tx = tid & 15, ty = tid >> 4;
    const int row0 = blockIdx.x * GTM, col0 = blockIdx.y * GTN;

    float acc[8][4];
#pragma unroll
    for (int r = 0; r < 8; ++r)
#pragma unroll
        for (int c = 0; c < 4; ++c) acc[r][c] = 0.f;

    for (int k0 = 0; k0 < HID; k0 += GTK) {
#pragma unroll
        for (int lidx = 0; lidx < (GTM*GTK)/256; ++lidx) {
            int idx = tid + lidx * 256;
            int r = idx >> 4, kk = idx & 15;
            As[kk][r] = A[(size_t)(row0 + r) * HID + k0 + kk];
        }
#pragma unroll
        for (int lidx = 0; lidx < (GTK*GTN)/256; ++lidx) {
            int idx = tid + lidx * 256;
            int kk = idx >> 6, c = idx & 63;
            Bs[kk][c] = W[(size_t)(k0 + kk) * HID + col0 + c];
        }
        __syncthreads();
#pragma unroll
        for (int kk = 0; kk < GTK; ++kk) {
            float4 b4 = *(const float4*)&Bs[kk][tx * 4];
            float4 a0 = *(const float4*)&As[kk][ty * 8];
            float4 a1 = *(const float4*)&As[kk][ty * 8 + 4];
            float a[8] = {a0.x,a0.y,a0.z,a0.w,a1.x,a1.y,a1.z,a1.w};
            float b[4] = {b4.x,b4.y,b4.z,b4.w};
#pragma unroll
            for (int r = 0; r < 8; ++r)
#pragma unroll
                for (int c = 0; c < 4; ++c) acc[r][c] += a[r] * b[c];
        }
        __syncthreads();
    }

#pragma unroll
    for (int r = 0; r < 8; ++r) {
        int row = row0 + ty * 8 + r;
#pragma unroll
        for (int c = 0; c < 4; ++c) {
            int col = col0 + tx * 4 + c;
            float v = acc[r][c] + bias[col];
            if (headLayout) {
                int bb = row >> 9, ll = row & 511, h = col >> 6, dd = col & 63;
                Cout[(((size_t)bb * NH + h) * L + ll) * D + dd] = v;
            } else {
                Cout[(size_t)row * HID + col] = v;
            }
        }
    }
}

// ------------- bias-table projection: P[bh][l][t] ---------------------------
// P[l][t] = q_l . EQ[t] + k_l . EK[t],  EQ = {query_hop | query_edge}, EK = {key_hop | key_edge}
__global__ __launch_bounds__(256) void proj_kernel(
    const float* __restrict__ qh, const float* __restrict__ qe,
    const float* __restrict__ kh, const float* __restrict__ ke)
{
    extern __shared__ float sm[];
    float* qs = sm;              // 64*64
    float* ks = qs + 64*64;      // 64*64
    float* EQ = ks + 64*64;      // 96*65 (padded)
    float* EK = EQ + TT*65;      // 96*65

    const int bh = blockIdx.x;
    const int h  = bh % NH;
    const int l0 = blockIdx.y * 64;
    const int tid = threadIdx.x;

    const float* Qp = g_Q + ((size_t)bh * L + l0) * D;
    const float* Kp = g_K + ((size_t)bh * L + l0) * D;
    for (int idx = tid; idx < 64 * D; idx += 256) { qs[idx] = Qp[idx]; ks[idx] = Kp[idx]; }
    for (int idx = tid; idx < TT * D; idx += 256) {
        int t = idx >> 6, dd = idx & 63;
        float eq, ek;
        if (t < TH) { eq = qh[(size_t)t * HID + h * D + dd]; ek = kh[(size_t)t * HID + h * D + dd]; }
        else        { eq = qe[(size_t)(t - TH) * HID + h * D + dd]; ek = ke[(size_t)(t - TH) * HID + h * D + dd]; }
        EQ[t * 65 + dd] = eq; EK[t * 65 + dd] = ek;
    }
    __syncthreads();

    float* Pout = g_P + ((size_t)bh * L + l0) * TT;
    for (int p = tid; p < 64 * TT; p += 256) {
        int ll = p / TT, t = p % TT;
        float s = 0.f;
#pragma unroll
        for (int dd = 0; dd < D; ++dd)
            s += qs[ll * D + dd] * EQ[t * 65 + dd] + ks[ll * D + dd] * EK[t * 65 + dd];
        Pout[ll * TT + t] = s;
    }
}

// ------------- attention: scores + gathered bias + softmax + AV + type-values
#define AT_ROWS 32
#define ATT_SMEM_FLOATS (AT_ROWS*512 + AT_ROWS*64 + AT_ROWS*TT + AT_ROWS*TT + TT*65)

__global__ __launch_bounds__(256) void attn_kernel(
    const int* __restrict__ hop, const int* __restrict__ edge,
    const float* __restrict__ vh, const float* __restrict__ ve)
{
    extern __shared__ float sm[];
    float* sc   = sm;                    // [32][512] scores -> att
    float* qs   = sc + AT_ROWS * 512;    // [32][64]
    float* Ps   = qs + AT_ROWS * 64;     // [32][96]
    float* bins = Ps + AT_ROWS * TT;     // [32][96]
    float* buf  = bins + AT_ROWS * TT;   // [96][65] shared staging (K chunk / V chunk / VE)

    const int bh = blockIdx.y;
    const int bb = bh / NH, h = bh % NH;
    const int i0 = blockIdx.x * AT_ROWS;
    const int tid = threadIdx.x;
    const float scale = 0.125f;          // 1/sqrt(64)

    // load Q rows + bias table, zero bins
    {
        const float* Qp = g_Q + ((size_t)bh * L + i0) * D;
        for (int idx = tid; idx < AT_ROWS * D; idx += 256) qs[idx] = Qp[idx];
        const float* Pp = g_P + ((size_t)bh * L + i0) * TT;
        for (int idx = tid; idx < AT_ROWS * TT; idx += 256) { Ps[idx] = Pp[idx]; bins[idx] = 0.f; }
    }

    const size_t hopBase = ((size_t)bb * L + i0) * L;

    // ---- scores ----
    for (int jc = 0; jc < L; jc += 64) {
        const float* Kp = g_K + ((size_t)bh * L + jc) * D;
        for (int idx = tid; idx < 64 * D; idx += 256)
            buf[(idx >> 6) * 65 + (idx & 63)] = Kp[idx];
        __syncthreads();
        for (int p = tid; p < AT_ROWS * 64; p += 256) {
            int i = p >> 6, j = p & 63;
            float s = 0.f;
#pragma unroll
            for (int dd = 0; dd < D; ++dd) s += qs[i * D + dd] * buf[j * 65 + dd];
            int jg = jc + j;
            int hv = hop [hopBase + (size_t)i * L + jg];
            int ev = edge[hopBase + (size_t)i * L + jg];
            s += Ps[i * TT + hv] + Ps[i * TT + TH + ev];
            sc[i * 512 + jg] = s;
        }
        __syncthreads();
    }

    // ---- softmax (row-per-warp groups) + scatter into type bins ----
    {
        const int warp = tid >> 5, lane = tid & 31;
        for (int i = warp * 4; i < warp * 4 + 4; ++i) {
            float m = -1e30f;
            for (int j = lane; j < L; j += 32) m = fmaxf(m, sc[i * 512 + j]);
#pragma unroll
            for (int off = 16; off > 0; off >>= 1) m = fmaxf(m, __shfl_xor_sync(0xffffffffu, m, off));
            float sum = 0.f;
            for (int j = lane; j < L; j += 32) {
                float e = __expf((sc[i * 512 + j] - m) * scale);
                sc[i * 512 + j] = e;
                sum += e;
            }
#pragma unroll
            for (int off = 16; off > 0; off >>= 1) sum += __shfl_xor_sync(0xffffffffu, sum, off);
            float rinv = 1.f / sum;
            const int* hr = hop  + hopBase + (size_t)i * L;
            const int* er = edge + hopBase + (size_t)i * L;
            for (int j = lane; j < L; j += 32) {
                float a = sc[i * 512 + j] * rinv;
                sc[i * 512 + j] = a;
                atomicAdd(&bins[i * TT + hr[j]], a);
                atomicAdd(&bins[i * TT + TH + er[j]], a);
            }
        }
    }
    __syncthreads();

    // ---- AV + type-value contribution ----
    const int dd = tid & 63;
    const int ib = tid >> 6;            // 0..3
    float acc[8];
#pragma unroll
    for (int k2 = 0; k2 < 8; ++k2) acc[k2] = 0.f;

    for (int jc = 0; jc < L; jc += 64) {
        const float* Vp = g_V + ((size_t)bh * L + jc) * D;
        for (int idx = tid; idx < 64 * D; idx += 256)
            buf[(idx >> 6) * 65 + (idx & 63)] = Vp[idx];
        __syncthreads();
        for (int j = 0; j < 64; ++j) {
            float bvv = buf[j * 65 + dd];
#pragma unroll
            for (int k2 = 0; k2 < 8; ++k2)
                acc[k2] += sc[(ib + 4 * k2) * 512 + jc + j] * bvv;
        }
        __syncthreads();
    }

    // type-value embeddings -> buf
    for (int idx = tid; idx < TT * D; idx += 256) {
        int t = idx >> 6, d2 = idx & 63;
        buf[t * 65 + d2] = (t < TH) ? vh[(size_t)t * HID + h * D + d2]
                                    : ve[(size_t)(t - TH) * HID + h * D + d2];
    }
    __syncthreads();
    for (int t = 0; t < TT; ++t) {
        float bvv = buf[t * 65 + dd];
#pragma unroll
        for (int k2 = 0; k2 < 8; ++k2)
            acc[k2] += bins[(ib + 4 * k2) * TT + t] * bvv;
    }

#pragma unroll
    for (int k2 = 0; k2 < 8; ++k2) {
        int i = ib + 4 * k2;
        g_AO[((size_t)bb * L + i0 + i) * HID + h * D + dd] = acc[k2];
    }
}

// --------------------------------------------------------------------------
extern "C" void kernel_launch(void* const* d_in, const int* in_sizes, int n_in,
                              void* d_out, int out_size)
{
    const float* x   = (const float*)d_in[0];
    const float* qh  = (const float*)d_in[1];
    const float* qe  = (const float*)d_in[2];
    const float* kh  = (const float*)d_in[3];
    const float* ke  = (const float*)d_in[4];
    const float* vh  = (const float*)d_in[5];
    const float* ve  = (const float*)d_in[6];
    const int*   hop = (const int*)d_in[7];
    const int*   edg = (const int*)d_in[8];
    const float* Wq = (const float*)d_in[9];   const float* bq = (const float*)d_in[10];
    const float* Wk = (const float*)d_in[11];  const float* bk = (const float*)d_in[12];
    const float* Wv = (const float*)d_in[13];  const float* bv = (const float*)d_in[14];
    const float* Wo = (const float*)d_in[15];  const float* bo = (const float*)d_in[16];
    float* out = (float*)d_out;

    float *Qp, *Kp, *Vp, *AOp;
    cudaGetSymbolAddress((void**)&Qp,  g_Q);
    cudaGetSymbolAddress((void**)&Kp,  g_K);
    cudaGetSymbolAddress((void**)&Vp,  g_V);
    cudaGetSymbolAddress((void**)&AOp, g_AO);

    const int projSmem = (64*64*2 + TT*65*2) * (int)sizeof(float);
    const int attSmem  = ATT_SMEM_FLOATS * (int)sizeof(float);
    cudaFuncSetAttribute(proj_kernel, cudaFuncAttributeMaxDynamicSharedMemorySize, projSmem);
    cudaFuncSetAttribute(attn_kernel, cudaFuncAttributeMaxDynamicSharedMemorySize, attSmem);

    dim3 gb(ROWS / GTM, HID / GTN);

    gemm_kernel<<<gb, 256>>>(x, Wq, bq, Qp, 1);
    gemm_kernel<<<gb, 256>>>(x, Wk, bk, Kp, 1);
    gemm_kernel<<<gb, 256>>>(x, Wv, bv, Vp, 1);
    proj_kernel<<<dim3(BH, L / 64), 256, projSmem>>>(qh, qe, kh, ke);
    attn_kernel<<<dim3(L / AT_ROWS, BH), 256, attSmem>>>(hop, edg, vh, ve);
    gemm_kernel<<<gb, 256>>>(AOp, Wo, bo, out, 0);
}